// round 10
// baseline (speedup 1.0000x reference)
#include <cuda_runtime.h>
#include <cuda_bf16.h>
#include <cuda_fp16.h>
#include <cstdint>

// ============================================================================
// Multihead_Attention (no-softmax => fully linear) on sm_100 (generic PTX).
// R10: 2 CTAs/SM GEMMs (tile 128x128) to overlap barrier/wait bubbles
//      (tensor pipe measured at only 56.4% in R9).
//      QKV: fp16 2-limb (BK=32, 3 stages, 90KB). Out: bf16 3-pass (BK=64,
//      3 stages, 108KB, single wave at 2 CTAs/SM).
// ============================================================================

#define MROWS 4096
#define DMODEL 1024

// fp32 intermediates
__device__ float g_Q[MROWS * DMODEL];
__device__ float g_K[MROWS * DMODEL];
__device__ float g_V[MROWS * DMODEL];
__device__ float g_Mpart[32 * 32 * 64 * 64];
__device__ float g_M[32 * 64 * 64];

// fp16 split operands (QKV path)
__device__ __half g_xh[MROWS * DMODEL], g_xl[MROWS * DMODEL];
__device__ __half g_yh[MROWS * DMODEL], g_yl[MROWS * DMODEL];
__device__ __half g_qwh[DMODEL * DMODEL];
__device__ __half g_kwh[DMODEL * DMODEL];
__device__ __half g_vwh[DMODEL * DMODEL];

// bf16 split operands (output-projection path, 3-pass)
__device__ __nv_bfloat16 g_oh[MROWS * DMODEL], g_ol[MROWS * DMODEL];
__device__ __nv_bfloat16 g_owh[DMODEL * DMODEL], g_owl[DMODEL * DMODEL];

// ---------------- generic PTX helpers ---------------------------------------
__device__ __forceinline__ uint32_t smem_u32(const void* p) {
    uint32_t a;
    asm("{ .reg .u64 t; cvta.to.shared.u64 t, %1; cvt.u32.u64 %0, t; }"
        : "=r"(a) : "l"(p));
    return a;
}
__device__ __forceinline__ void cp16(uint32_t dst, const void* src) {
    asm volatile("cp.async.cg.shared.global [%0], [%1], 16;"
                 :: "r"(dst), "l"(src) : "memory");
}
__device__ __forceinline__ void ldsm4(uint32_t (&r)[4], uint32_t addr) {
    asm volatile("ldmatrix.sync.aligned.m8n8.x4.shared.b16 {%0,%1,%2,%3}, [%4];"
                 : "=r"(r[0]), "=r"(r[1]), "=r"(r[2]), "=r"(r[3]) : "r"(addr));
}
__device__ __forceinline__ void mma_bf16(float (&d)[4], const uint32_t (&a)[4],
                                         uint32_t b0, uint32_t b1) {
    asm volatile(
        "mma.sync.aligned.m16n8k16.row.col.f32.bf16.bf16.f32 "
        "{%0,%1,%2,%3}, {%4,%5,%6,%7}, {%8,%9}, {%0,%1,%2,%3};"
        : "+f"(d[0]), "+f"(d[1]), "+f"(d[2]), "+f"(d[3])
        : "r"(a[0]), "r"(a[1]), "r"(a[2]), "r"(a[3]), "r"(b0), "r"(b1));
}
__device__ __forceinline__ void mma_f16(float (&d)[4], const uint32_t (&a)[4],
                                        uint32_t b0, uint32_t b1) {
    asm volatile(
        "mma.sync.aligned.m16n8k16.row.col.f32.f16.f16.f32 "
        "{%0,%1,%2,%3}, {%4,%5,%6,%7}, {%8,%9}, {%0,%1,%2,%3};"
        : "+f"(d[0]), "+f"(d[1]), "+f"(d[2]), "+f"(d[3])
        : "r"(a[0]), "r"(a[1]), "r"(a[2]), "r"(a[3]), "r"(b0), "r"(b1));
}

// ---------------- f32x2 helpers ---------------------------------------------
__device__ __forceinline__ unsigned long long f32x2_dup(float x) {
    unsigned long long r; asm("mov.b64 %0, {%1, %1};" : "=l"(r) : "f"(x)); return r;
}
__device__ __forceinline__ unsigned long long f32x2_pack(float x, float y) {
    unsigned long long r; asm("mov.b64 %0, {%1, %2};" : "=l"(r) : "f"(x), "f"(y)); return r;
}
__device__ __forceinline__ unsigned long long f32x2_fma(unsigned long long a,
                                                        unsigned long long b,
                                                        unsigned long long c) {
    unsigned long long d;
    asm("fma.rn.f32x2 %0, %1, %2, %3;" : "=l"(d) : "l"(a), "l"(b), "l"(c));
    return d;
}
__device__ __forceinline__ float2 f32x2_unpack(unsigned long long v) {
    float2 r; asm("mov.b64 {%0, %1}, %2;" : "=f"(r.x), "=f"(r.y) : "l"(v)); return r;
}

// pack 4 fp32 -> bf16 hi uint2 + lo uint2
__device__ __forceinline__ void split4_bf16(float4 v, uint2& hv, uint2& lv) {
    __nv_bfloat16 h0 = __float2bfloat16(v.x), h1 = __float2bfloat16(v.y);
    __nv_bfloat16 h2 = __float2bfloat16(v.z), h3 = __float2bfloat16(v.w);
    __nv_bfloat16 l0 = __float2bfloat16(v.x - __bfloat162float(h0));
    __nv_bfloat16 l1 = __float2bfloat16(v.y - __bfloat162float(h1));
    __nv_bfloat16 l2 = __float2bfloat16(v.z - __bfloat162float(h2));
    __nv_bfloat16 l3 = __float2bfloat16(v.w - __bfloat162float(h3));
    __nv_bfloat162 hp0 = {h0, h1}, hp1 = {h2, h3};
    __nv_bfloat162 lp0 = {l0, l1}, lp1 = {l2, l3};
    hv.x = *reinterpret_cast<uint32_t*>(&hp0); hv.y = *reinterpret_cast<uint32_t*>(&hp1);
    lv.x = *reinterpret_cast<uint32_t*>(&lp0); lv.y = *reinterpret_cast<uint32_t*>(&lp1);
}

// pack 4 fp32 -> fp16 hi uint2 + lo uint2
__device__ __forceinline__ void split4_f16(float4 v, uint2& hv, uint2& lv) {
    __half h0 = __float2half_rn(v.x), h1 = __float2half_rn(v.y);
    __half h2 = __float2half_rn(v.z), h3 = __float2half_rn(v.w);
    __half l0 = __float2half_rn(v.x - __half2float(h0));
    __half l1 = __float2half_rn(v.y - __half2float(h1));
    __half l2 = __float2half_rn(v.z - __half2float(h2));
    __half l3 = __float2half_rn(v.w - __half2float(h3));
    __half2 hp0 = {h0, h1}, hp1 = {h2, h3};
    __half2 lp0 = {l0, l1}, lp1 = {l2, l3};
    hv.x = *reinterpret_cast<uint32_t*>(&hp0); hv.y = *reinterpret_cast<uint32_t*>(&hp1);
    lv.x = *reinterpret_cast<uint32_t*>(&lp0); lv.y = *reinterpret_cast<uint32_t*>(&lp1);
}

// ============================================================================
// splits
// ============================================================================
__global__ __launch_bounds__(256)
void split_act_f16(const float* __restrict__ x, const float* __restrict__ y,
                   __half* __restrict__ xh, __half* __restrict__ xl,
                   __half* __restrict__ yh, __half* __restrict__ yl) {
    const float* src = blockIdx.y ? y : x;
    __half* hi = blockIdx.y ? yh : xh;
    __half* lo = blockIdx.y ? yl : xl;
    int i = blockIdx.x * 256 + threadIdx.x;
    float4 v = reinterpret_cast<const float4*>(src)[i];
    uint2 hv, lv;
    split4_f16(v, hv, lv);
    reinterpret_cast<uint2*>(hi)[i] = hv;
    reinterpret_cast<uint2*>(lo)[i] = lv;
}

__global__ __launch_bounds__(256)
void split_wqkv_f16(const float* __restrict__ w0, const float* __restrict__ w1,
                    const float* __restrict__ w2,
                    __half* __restrict__ h0, __half* __restrict__ h1,
                    __half* __restrict__ h2) {
    const float* src = (blockIdx.y == 0) ? w0 : (blockIdx.y == 1) ? w1 : w2;
    __half* hi = (blockIdx.y == 0) ? h0 : (blockIdx.y == 1) ? h1 : h2;
    int i = blockIdx.x * 256 + threadIdx.x;
    float4 v = reinterpret_cast<const float4*>(src)[i];
    __half a = __float2half_rn(v.x), b = __float2half_rn(v.y);
    __half c = __float2half_rn(v.z), d = __float2half_rn(v.w);
    __half2 p0 = {a, b}, p1 = {c, d};
    uint2 hv = {*reinterpret_cast<uint32_t*>(&p0), *reinterpret_cast<uint32_t*>(&p1)};
    reinterpret_cast<uint2*>(hi)[i] = hv;
}

__global__ __launch_bounds__(256)
void split_ow_bf16(const float* __restrict__ w,
                   __nv_bfloat16* __restrict__ hi, __nv_bfloat16* __restrict__ lo) {
    int i = blockIdx.x * 256 + threadIdx.x;
    float4 v = reinterpret_cast<const float4*>(w)[i];
    uint2 hv, lv;
    split4_bf16(v, hv, lv);
    reinterpret_cast<uint2*>(hi)[i] = hv;
    reinterpret_cast<uint2*>(lo)[i] = lv;
}

// ============================================================================
// fp16 2-limb QKV GEMM, 2 CTAs/SM: C = (Ah + Al) @ Wh^T + bias
// CTA tile 128(M) x 128(N), BK=32, 3-stage cp.async, 8 warps (warp 32x64).
// 32 mainloop iters; per kc: 8 ldsm4 + 32 mma (2 limbs share one accum).
// SMEM rows 80B padded. Stage = Ah(10240)+Al(10240)+W(10240); 3 stages = 90KB.
// ============================================================================
#define FQ_ST 10240
#define FQ_AL_BASE (3 * FQ_ST)            // 30720
#define FQ_W_BASE  (6 * FQ_ST)            // 61440
#define FQ_TOTAL   (9 * FQ_ST)            // 92160

__global__ __launch_bounds__(256, 2)
void gemm_qkv_f16(const __half* __restrict__ xh, const __half* __restrict__ xl,
                  const __half* __restrict__ yh, const __half* __restrict__ yl,
                  const __half* __restrict__ qwh, const __half* __restrict__ kwh,
                  const __half* __restrict__ vwh,
                  const float* __restrict__ q_b, const float* __restrict__ k_b,
                  const float* __restrict__ v_b,
                  float* __restrict__ Q, float* __restrict__ K, float* __restrict__ V) {
    extern __shared__ __align__(128) char smem[];
    __shared__ float biasS[128];
    const uint32_t sbase = smem_u32(smem);
    const int tid = threadIdx.x;
    const int lane = tid & 31;
    const int wid = tid >> 5;
    const int n0 = blockIdx.x << 7;   // 128-wide N tile
    const int m0 = blockIdx.y << 7;
    const int z = blockIdx.z;

    const __half* Ah = (z == 2) ? yh : xh;
    const __half* Al = (z == 2) ? yl : xl;
    const __half* Wh = (z == 0) ? qwh : (z == 1) ? kwh : vwh;
    const float* bias = (z == 0) ? q_b : (z == 1) ? k_b : v_b;
    float* C = (z == 0) ? Q : (z == 1) ? K : V;

    if (tid < 128) biasS[tid] = bias[n0 + tid];

    // stage load: BK=32 fp16 = 64B/row = 4 x 16B chunks; 128 rows = 512 chunks
    auto load_stage = [&](int kt, int s) {
        const int kcol = kt << 5;
        const uint32_t sah = sbase + s * FQ_ST;
        const uint32_t sal = sbase + FQ_AL_BASE + s * FQ_ST;
        const uint32_t sb = sbase + FQ_W_BASE + s * FQ_ST;
#pragma unroll
        for (int u = 0; u < 2; u++) {
            int idx = tid + (u << 8);
            int r = idx >> 2, c = idx & 3;
            cp16(sah + r * 80 + c * 16, Ah + (m0 + r) * DMODEL + kcol + c * 8);
            cp16(sal + r * 80 + c * 16, Al + (m0 + r) * DMODEL + kcol + c * 8);
            cp16(sb + r * 80 + c * 16, Wh + (n0 + r) * DMODEL + kcol + c * 8);
        }
    };

    load_stage(0, 0);
    asm volatile("cp.async.commit_group;" ::: "memory");
    load_stage(1, 1);
    asm volatile("cp.async.commit_group;" ::: "memory");

    float d[2][8][4];
#pragma unroll
    for (int mf = 0; mf < 2; mf++)
#pragma unroll
        for (int nf = 0; nf < 8; nf++)
#pragma unroll
            for (int q = 0; q < 4; q++) d[mf][nf][q] = 0.f;

    const int warpM = (wid & 3) << 5;    // 0,32,64,96
    const int warpN = (wid >> 2) << 6;   // 0,64
    const uint32_t aLane = (warpM + (lane & 15)) * 80 + (lane >> 4) * 16;
    const uint32_t bLane = (warpN + ((lane >> 4) & 1) * 8 + (lane & 7)) * 80 +
                           ((lane >> 3) & 1) * 16;

    for (int it = 0; it < 32; ++it) {
        const int buf = it % 3;
        if (it < 31)
            asm volatile("cp.async.wait_group 1;" ::: "memory");
        else
            asm volatile("cp.async.wait_group 0;" ::: "memory");
        __syncthreads();
        if (it + 2 < 32) {
            load_stage(it + 2, (it + 2) % 3);
            asm volatile("cp.async.commit_group;" ::: "memory");
        }
        const uint32_t sah = sbase + buf * FQ_ST + aLane;
        const uint32_t sal = sbase + FQ_AL_BASE + buf * FQ_ST + aLane;
        const uint32_t sb = sbase + FQ_W_BASE + buf * FQ_ST + bLane;

#pragma unroll
        for (int kc = 0; kc < 2; kc++) {
            const uint32_t ko = kc * 32;
            uint32_t ah[2][4], al[2][4], bb[4][4];
            ldsm4(ah[0], sah + ko); ldsm4(ah[1], sah + 1280 + ko);
            ldsm4(al[0], sal + ko); ldsm4(al[1], sal + 1280 + ko);
            ldsm4(bb[0], sb + ko); ldsm4(bb[1], sb + 1280 + ko);
            ldsm4(bb[2], sb + 2560 + ko); ldsm4(bb[3], sb + 3840 + ko);
#pragma unroll
            for (int mf = 0; mf < 2; mf++)
#pragma unroll
                for (int nf = 0; nf < 8; nf++)
                    mma_f16(d[mf][nf], ah[mf], bb[nf >> 1][(nf & 1) * 2],
                            bb[nf >> 1][(nf & 1) * 2 + 1]);
#pragma unroll
            for (int mf = 0; mf < 2; mf++)
#pragma unroll
                for (int nf = 0; nf < 8; nf++)
                    mma_f16(d[mf][nf], al[mf], bb[nf >> 1][(nf & 1) * 2],
                            bb[nf >> 1][(nf & 1) * 2 + 1]);
        }
    }

    const int rsub = lane >> 2;
    const int csub = (lane & 3) * 2;
#pragma unroll
    for (int mf = 0; mf < 2; mf++) {
#pragma unroll
        for (int nf = 0; nf < 8; nf++) {
            const int row = m0 + warpM + mf * 16 + rsub;
            const int colL = warpN + nf * 8 + csub;
            const float b0 = biasS[colL], b1 = biasS[colL + 1];
            float2 v0 = make_float2(d[mf][nf][0] + b0, d[mf][nf][1] + b1);
            float2 v1 = make_float2(d[mf][nf][2] + b0, d[mf][nf][3] + b1);
            *reinterpret_cast<float2*>(&C[(size_t)row * DMODEL + n0 + colL]) = v0;
            *reinterpret_cast<float2*>(&C[(size_t)(row + 8) * DMODEL + n0 + colL]) = v1;
        }
    }
}

// ============================================================================
// bf16 3-pass output GEMM, 2 CTAs/SM: tile 128x128, BK=64, 3 stages.
// 48 iters (3 passes x 16). Stage = A(18432) + W(18432); 3 stages = 108KB.
// ============================================================================
#define GO_ST 18432
#define GO_W_BASE (3 * GO_ST)             // 55296
#define GO_TOTAL  (6 * GO_ST)             // 110592

__global__ __launch_bounds__(256, 2)
void gemm_out_bf16(const __nv_bfloat16* __restrict__ Ah, const __nv_bfloat16* __restrict__ Al,
                   const __nv_bfloat16* __restrict__ Wh, const __nv_bfloat16* __restrict__ Wl,
                   const float* __restrict__ bias, float* __restrict__ C) {
    extern __shared__ __align__(128) char smem[];
    __shared__ float biasS[128];
    const uint32_t sbase = smem_u32(smem);
    const int tid = threadIdx.x;
    const int lane = tid & 31;
    const int wid = tid >> 5;
    const int n0 = blockIdx.x << 7;
    const int m0 = blockIdx.y << 7;

    if (tid < 128) biasS[tid] = bias[n0 + tid];

    // stage load: BK=64 bf16 = 128B/row = 8 x 16B chunks; 128 rows = 1024 chunks
    auto load_stage = [&](int it, int s) {
        const int p = it >> 4;
        const int kcol = (it & 15) << 6;
        const __nv_bfloat16* ap = (p == 1) ? Al : Ah;
        const __nv_bfloat16* wp = (p == 2) ? Wl : Wh;
        const uint32_t sa = sbase + s * GO_ST;
        const uint32_t sb = sbase + GO_W_BASE + s * GO_ST;
#pragma unroll
        for (int u = 0; u < 4; u++) {
            int idx = tid + (u << 8);
            int r = idx >> 3, c = idx & 7;
            cp16(sa + r * 144 + c * 16, ap + (m0 + r) * DMODEL + kcol + c * 8);
            cp16(sb + r * 144 + c * 16, wp + (n0 + r) * DMODEL + kcol + c * 8);
        }
    };

    load_stage(0, 0);
    asm volatile("cp.async.commit_group;" ::: "memory");
    load_stage(1, 1);
    asm volatile("cp.async.commit_group;" ::: "memory");

    float d[2][8][4];
#pragma unroll
    for (int mf = 0; mf < 2; mf++)
#pragma unroll
        for (int nf = 0; nf < 8; nf++)
#pragma unroll
            for (int q = 0; q < 4; q++) d[mf][nf][q] = 0.f;

    const int warpM = (wid & 3) << 5;
    const int warpN = (wid >> 2) << 6;
    const uint32_t aLane = (warpM + (lane & 15)) * 144 + (lane >> 4) * 16;
    const uint32_t bLane = (warpN + ((lane >> 4) & 1) * 8 + (lane & 7)) * 144 +
                           ((lane >> 3) & 1) * 16;

    for (int it = 0; it < 48; ++it) {
        const int buf = it % 3;
        if (it < 47)
            asm volatile("cp.async.wait_group 1;" ::: "memory");
        else
            asm volatile("cp.async.wait_group 0;" ::: "memory");
        __syncthreads();
        if (it + 2 < 48) {
            load_stage(it + 2, (it + 2) % 3);
            asm volatile("cp.async.commit_group;" ::: "memory");
        }
        const uint32_t sa = sbase + buf * GO_ST + aLane;
        const uint32_t sb = sbase + GO_W_BASE + buf * GO_ST + bLane;

#pragma unroll
        for (int kc = 0; kc < 4; kc++) {
            const uint32_t ko = kc * 32;
            uint32_t a[2][4], bb[4][4];
            ldsm4(a[0], sa + ko); ldsm4(a[1], sa + 2304 + ko);
            ldsm4(bb[0], sb + ko); ldsm4(bb[1], sb + 2304 + ko);
            ldsm4(bb[2], sb + 4608 + ko); ldsm4(bb[3], sb + 6912 + ko);
#pragma unroll
            for (int mf = 0; mf < 2; mf++)
#pragma unroll
                for (int nf = 0; nf < 8; nf++)
                    mma_bf16(d[mf][nf], a[mf], bb[nf >> 1][(nf & 1) * 2],
                             bb[nf >> 1][(nf & 1) * 2 + 1]);
        }
    }

    const int rsub = lane >> 2;
    const int csub = (lane & 3) * 2;
#pragma unroll
    for (int mf = 0; mf < 2; mf++) {
#pragma unroll
        for (int nf = 0; nf < 8; nf++) {
            const int row = m0 + warpM + mf * 16 + rsub;
            const int colL = warpN + nf * 8 + csub;
            const float b0 = biasS[colL], b1 = biasS[colL + 1];
            float2 v0 = make_float2(d[mf][nf][0] + b0, d[mf][nf][1] + b1);
            float2 v1 = make_float2(d[mf][nf][2] + b0, d[mf][nf][3] + b1);
            *reinterpret_cast<float2*>(&C[(size_t)row * DMODEL + n0 + colL]) = v0;
            *reinterpret_cast<float2*>(&C[(size_t)(row + 8) * DMODEL + n0 + colL]) = v1;
        }
    }
}

// ============================================================================
// compute_m_partial: Mpart[s][g] = sum over t in [s*64,(s+1)*64) Kg[t]^T Vg[t]
// grid (32, 32), 256 threads, 4x4 per thread.
// ============================================================================
__global__ __launch_bounds__(256)
void compute_m_partial(const float* __restrict__ Kb, const float* __restrict__ Vb,
                       float* __restrict__ Mpart) {
    const int s = blockIdx.x;
    const int g = blockIdx.y;
    __shared__ float Ks[32][64];
    __shared__ float Vs[32][64];

    const int tid = threadIdx.x;
    const int tx = tid & 15;
    const int ty = tid >> 4;

    const float* Kg = Kb + g * 131072 + s * 64 * 64;
    const float* Vg = Vb + g * 131072 + s * 64 * 64;

    unsigned long long acc[4][2];
#pragma unroll
    for (int i = 0; i < 4; i++) { acc[i][0] = 0ull; acc[i][1] = 0ull; }

    for (int t0 = 0; t0 < 64; t0 += 32) {
#pragma unroll
        for (int sr = 0; sr < 2; sr++) {
            int idx = tid + (sr << 8);
            int tt = idx >> 4;
            int d4 = (idx & 15) << 2;
            *reinterpret_cast<float4*>(&Ks[tt][d4]) =
                *reinterpret_cast<const float4*>(&Kg[(t0 + tt) * 64 + d4]);
            *reinterpret_cast<float4*>(&Vs[tt][d4]) =
                *reinterpret_cast<const float4*>(&Vg[(t0 + tt) * 64 + d4]);
        }
        __syncthreads();
#pragma unroll 8
        for (int tt = 0; tt < 32; tt++) {
            float4 a = *reinterpret_cast<const float4*>(&Ks[tt][ty << 2]);
            float4 b = *reinterpret_cast<const float4*>(&Vs[tt][tx << 2]);
            unsigned long long bq0 = f32x2_pack(b.x, b.y);
            unsigned long long bq1 = f32x2_pack(b.z, b.w);
            float av[4] = {a.x, a.y, a.z, a.w};
#pragma unroll
            for (int i = 0; i < 4; i++) {
                unsigned long long ad = f32x2_dup(av[i]);
                acc[i][0] = f32x2_fma(ad, bq0, acc[i][0]);
                acc[i][1] = f32x2_fma(ad, bq1, acc[i][1]);
            }
        }
        __syncthreads();
    }

#pragma unroll
    for (int i = 0; i < 4; i++) {
        float2 v0 = f32x2_unpack(acc[i][0]);
        float2 v1 = f32x2_unpack(acc[i][1]);
        int d = (ty << 2) + i;
        int dp = tx << 2;
        float4 o = make_float4(v0.x, v0.y, v1.x, v1.y);
        *reinterpret_cast<float4*>(&Mpart[(s * 32 + g) * 4096 + d * 64 + dp]) = o;
    }
}

__global__ __launch_bounds__(256)
void reduce_m(const float* __restrict__ Mpart, float* __restrict__ M) {
    int i = blockIdx.x * 256 + threadIdx.x;
    float acc = 0.f;
#pragma unroll
    for (int s = 0; s < 32; s++) acc += Mpart[s * 131072 + i];
    M[i] = acc * 0.03125f;
}

// ============================================================================
// apply_m: O[r, j*64+d'] = sum_d Q[r, j*64+d] * M[g][d][d'],  g = r/128
// Emits bf16 hi/lo directly (feeds bf16 output GEMM).
// ============================================================================
__global__ __launch_bounds__(256)
void apply_m(const float* __restrict__ Qb, const float* __restrict__ Mb,
             __nv_bfloat16* __restrict__ Oh, __nv_bfloat16* __restrict__ Ol) {
    const int j = blockIdx.x;
    const int g = blockIdx.y;

    __shared__ float Qs[64][128];
    __shared__ float Ms[64][64];

    const int tid = threadIdx.x;
    const int tx = tid & 15;
    const int ty = tid >> 4;

#pragma unroll
    for (int s = 0; s < 4; s++) {
        int idx = tid + (s << 8);
        *reinterpret_cast<float4*>(&Ms[idx >> 4][(idx & 15) << 2]) =
            *reinterpret_cast<const float4*>(&Mb[g * 4096 + idx * 4]);
    }
#pragma unroll
    for (int s = 0; s < 8; s++) {
        int idx = tid + (s << 8);
        int r = idx & 127;
        int d4 = (idx >> 7) << 2;
        float4 v = *reinterpret_cast<const float4*>(
            &Qb[(g * 128 + r) * DMODEL + (j << 6) + d4]);
        Qs[d4 + 0][r] = v.x; Qs[d4 + 1][r] = v.y;
        Qs[d4 + 2][r] = v.z; Qs[d4 + 3][r] = v.w;
    }
    __syncthreads();

    unsigned long long acc[8][2];
#pragma unroll
    for (int i = 0; i < 8; i++) { acc[i][0] = 0ull; acc[i][1] = 0ull; }

#pragma unroll 4
    for (int d = 0; d < 64; d++) {
        float4 a0 = *reinterpret_cast<const float4*>(&Qs[d][ty << 3]);
        float4 a1 = *reinterpret_cast<const float4*>(&Qs[d][(ty << 3) + 4]);
        float4 b = *reinterpret_cast<const float4*>(&Ms[d][tx << 2]);
        unsigned long long bq0 = f32x2_pack(b.x, b.y);
        unsigned long long bq1 = f32x2_pack(b.z, b.w);
        float av[8] = {a0.x, a0.y, a0.z, a0.w, a1.x, a1.y, a1.z, a1.w};
#pragma unroll
        for (int i = 0; i < 8; i++) {
            unsigned long long ad = f32x2_dup(av[i]);
            acc[i][0] = f32x2_fma(ad, bq0, acc[i][0]);
            acc[i][1] = f32x2_fma(ad, bq1, acc[i][1]);
        }
    }

#pragma unroll
    for (int i = 0; i < 8; i++) {
        int r = g * 128 + (ty << 3) + i;
        float2 v0 = f32x2_unpack(acc[i][0]);
        float2 v1 = f32x2_unpack(acc[i][1]);
        float4 o = make_float4(v0.x, v0.y, v1.x, v1.y);
        uint2 hv, lv;
        split4_bf16(o, hv, lv);
        int col = (j << 6) + (tx << 2);
        *reinterpret_cast<uint2*>(&Oh[r * DMODEL + col]) = hv;
        *reinterpret_cast<uint2*>(&Ol[r * DMODEL + col]) = lv;
    }
}

// ============================================================================
extern "C" void kernel_launch(void* const* d_in, const int* in_sizes, int n_in,
                              void* d_out, int out_size) {
    const float* x   = (const float*)d_in[0];
    const float* y   = (const float*)d_in[1];
    const float* q_w = (const float*)d_in[2];
    const float* q_b = (const float*)d_in[3];
    const float* k_w = (const float*)d_in[4];
    const float* k_b = (const float*)d_in[5];
    const float* v_w = (const float*)d_in[6];
    const float* v_b = (const float*)d_in[7];
    const float* o_w = (const float*)d_in[8];
    const float* o_b = (const float*)d_in[9];
    float* out = (float*)d_out;

    float *Qp, *Kp, *Vp, *Mpp, *Mp;
    cudaGetSymbolAddress((void**)&Qp, g_Q);
    cudaGetSymbolAddress((void**)&Kp, g_K);
    cudaGetSymbolAddress((void**)&Vp, g_V);
    cudaGetSymbolAddress((void**)&Mpp, g_Mpart);
    cudaGetSymbolAddress((void**)&Mp, g_M);

    __half *xh, *xl, *yh, *yl, *qwh, *kwh, *vwh;
    __nv_bfloat16 *oh, *ol, *owh, *owl;
    cudaGetSymbolAddress((void**)&xh, g_xh);  cudaGetSymbolAddress((void**)&xl, g_xl);
    cudaGetSymbolAddress((void**)&yh, g_yh);  cudaGetSymbolAddress((void**)&yl, g_yl);
    cudaGetSymbolAddress((void**)&qwh, g_qwh);
    cudaGetSymbolAddress((void**)&kwh, g_kwh);
    cudaGetSymbolAddress((void**)&vwh, g_vwh);
    cudaGetSymbolAddress((void**)&oh, g_oh);  cudaGetSymbolAddress((void**)&ol, g_ol);
    cudaGetSymbolAddress((void**)&owh, g_owh); cudaGetSymbolAddress((void**)&owl, g_owl);

    cudaFuncSetAttribute(gemm_qkv_f16, cudaFuncAttributeMaxDynamicSharedMemorySize,
                         FQ_TOTAL);
    cudaFuncSetAttribute(gemm_out_bf16, cudaFuncAttributeMaxDynamicSharedMemorySize,
                         GO_TOTAL);

    const int n4_act = MROWS * DMODEL / 4;    // 1048576
    const int n4_w = DMODEL * DMODEL / 4;     // 262144

    split_act_f16<<<dim3(n4_act / 256, 2), 256>>>(x, y, xh, xl, yh, yl);
    split_wqkv_f16<<<dim3(n4_w / 256, 3), 256>>>(q_w, k_w, v_w, qwh, kwh, vwh);
    split_ow_bf16<<<n4_w / 256, 256>>>(o_w, owh, owl);

    gemm_qkv_f16<<<dim3(DMODEL / 128, MROWS / 128, 3), 256, FQ_TOTAL>>>(
        xh, xl, yh, yl, qwh, kwh, vwh, q_b, k_b, v_b, Qp, Kp, Vp);

    compute_m_partial<<<dim3(32, 32), 256>>>(Kp, Vp, Mpp);
    reduce_m<<<512, 256>>>(Mpp, Mp);
    apply_m<<<dim3(16, 32), 256>>>(Qp, Mp, oh, ol);

    gemm_out_bf16<<<dim3(DMODEL / 128, MROWS / 128), 256, GO_TOTAL>>>(
        oh, ol, owh, owl, o_b, out);
}

// round 13
// speedup vs baseline: 1.1648x; 1.1648x over previous
#include <cuda_runtime.h>
#include <cuda_fp16.h>
#include <cstdint>

// ============================================================================
// Multihead_Attention (no-softmax => fully linear) on sm_100 (generic PTX).
// R13 == R11 == R12 (broker infra flake, bursty; same cadence as R7-R9 where
//      the 3rd identical submit passed and hit prediction):
//      ALL four GEMMs via fp16 2-limb asymmetric split (A = Ah+Al fp16 exact,
//      W single fp16). R9 tile config (128x256, BK=64, 1 CTA/SM) — R10 proved
//      the legacy mma.sync issue rate is the invariant binder, so minimize
//      MMA instruction count: 8 GEMM-pass units total (was 9).
// ============================================================================

#define MROWS 4096
#define DMODEL 1024

// fp32 intermediates
__device__ float g_Q[MROWS * DMODEL];
__device__ float g_K[MROWS * DMODEL];
__device__ float g_V[MROWS * DMODEL];
__device__ float g_Mpart[32 * 32 * 64 * 64];
__device__ float g_M[32 * 64 * 64];

// fp16 split operands
__device__ __half g_xh[MROWS * DMODEL], g_xl[MROWS * DMODEL];
__device__ __half g_yh[MROWS * DMODEL], g_yl[MROWS * DMODEL];
__device__ __half g_oh[MROWS * DMODEL], g_ol[MROWS * DMODEL];
__device__ __half g_qwh[DMODEL * DMODEL];
__device__ __half g_kwh[DMODEL * DMODEL];
__device__ __half g_vwh[DMODEL * DMODEL];
__device__ __half g_owh[DMODEL * DMODEL];

// ---------------- generic PTX helpers ---------------------------------------
__device__ __forceinline__ uint32_t smem_u32(const void* p) {
    uint32_t a;
    asm("{ .reg .u64 t; cvta.to.shared.u64 t, %1; cvt.u32.u64 %0, t; }"
        : "=r"(a) : "l"(p));
    return a;
}
__device__ __forceinline__ void cp16(uint32_t dst, const void* src) {
    asm volatile("cp.async.cg.shared.global [%0], [%1], 16;"
                 :: "r"(dst), "l"(src) : "memory");
}
__device__ __forceinline__ void ldsm4(uint32_t (&r)[4], uint32_t addr) {
    asm volatile("ldmatrix.sync.aligned.m8n8.x4.shared.b16 {%0,%1,%2,%3}, [%4];"
                 : "=r"(r[0]), "=r"(r[1]), "=r"(r[2]), "=r"(r[3]) : "r"(addr));
}
__device__ __forceinline__ void mma_f16(float (&d)[4], const uint32_t (&a)[4],
                                        uint32_t b0, uint32_t b1) {
    asm volatile(
        "mma.sync.aligned.m16n8k16.row.col.f32.f16.f16.f32 "
        "{%0,%1,%2,%3}, {%4,%5,%6,%7}, {%8,%9}, {%0,%1,%2,%3};"
        : "+f"(d[0]), "+f"(d[1]), "+f"(d[2]), "+f"(d[3])
        : "r"(a[0]), "r"(a[1]), "r"(a[2]), "r"(a[3]), "r"(b0), "r"(b1));
}

// ---------------- f32x2 helpers ---------------------------------------------
__device__ __forceinline__ unsigned long long f32x2_dup(float x) {
    unsigned long long r; asm("mov.b64 %0, {%1, %1};" : "=l"(r) : "f"(x)); return r;
}
__device__ __forceinline__ unsigned long long f32x2_pack(float x, float y) {
    unsigned long long r; asm("mov.b64 %0, {%1, %2};" : "=l"(r) : "f"(x), "f"(y)); return r;
}
__device__ __forceinline__ unsigned long long f32x2_fma(unsigned long long a,
                                                        unsigned long long b,
                                                        unsigned long long c) {
    unsigned long long d;
    asm("fma.rn.f32x2 %0, %1, %2, %3;" : "=l"(d) : "l"(a), "l"(b), "l"(c));
    return d;
}
__device__ __forceinline__ float2 f32x2_unpack(unsigned long long v) {
    float2 r; asm("mov.b64 {%0, %1}, %2;" : "=f"(r.x), "=f"(r.y) : "l"(v)); return r;
}

// pack 4 fp32 -> fp16 hi uint2 + lo uint2
__device__ __forceinline__ void split4_f16(float4 v, uint2& hv, uint2& lv) {
    __half h0 = __float2half_rn(v.x), h1 = __float2half_rn(v.y);
    __half h2 = __float2half_rn(v.z), h3 = __float2half_rn(v.w);
    __half l0 = __float2half_rn(v.x - __half2float(h0));
    __half l1 = __float2half_rn(v.y - __half2float(h1));
    __half l2 = __float2half_rn(v.z - __half2float(h2));
    __half l3 = __float2half_rn(v.w - __half2float(h3));
    __half2 hp0 = {h0, h1}, hp1 = {h2, h3};
    __half2 lp0 = {l0, l1}, lp1 = {l2, l3};
    hv.x = *reinterpret_cast<uint32_t*>(&hp0); hv.y = *reinterpret_cast<uint32_t*>(&hp1);
    lv.x = *reinterpret_cast<uint32_t*>(&lp0); lv.y = *reinterpret_cast<uint32_t*>(&lp1);
}

// ============================================================================
// splits
// ============================================================================
__global__ __launch_bounds__(256)
void split_act_f16(const float* __restrict__ x, const float* __restrict__ y,
                   __half* __restrict__ xh, __half* __restrict__ xl,
                   __half* __restrict__ yh, __half* __restrict__ yl) {
    const float* src = blockIdx.y ? y : x;
    __half* hi = blockIdx.y ? yh : xh;
    __half* lo = blockIdx.y ? yl : xl;
    int i = blockIdx.x * 256 + threadIdx.x;
    float4 v = reinterpret_cast<const float4*>(src)[i];
    uint2 hv, lv;
    split4_f16(v, hv, lv);
    reinterpret_cast<uint2*>(hi)[i] = hv;
    reinterpret_cast<uint2*>(lo)[i] = lv;
}

// all 4 weights -> single fp16
__global__ __launch_bounds__(256)
void split_w_f16(const float* __restrict__ w0, const float* __restrict__ w1,
                 const float* __restrict__ w2, const float* __restrict__ w3,
                 __half* __restrict__ h0, __half* __restrict__ h1,
                 __half* __restrict__ h2, __half* __restrict__ h3) {
    const float* src = (blockIdx.y == 0) ? w0 : (blockIdx.y == 1) ? w1
                       : (blockIdx.y == 2) ? w2 : w3;
    __half* hi = (blockIdx.y == 0) ? h0 : (blockIdx.y == 1) ? h1
                 : (blockIdx.y == 2) ? h2 : h3;
    int i = blockIdx.x * 256 + threadIdx.x;
    float4 v = reinterpret_cast<const float4*>(src)[i];
    __half a = __float2half_rn(v.x), b = __float2half_rn(v.y);
    __half c = __float2half_rn(v.z), d = __float2half_rn(v.w);
    __half2 p0 = {a, b}, p1 = {c, d};
    uint2 hv = {*reinterpret_cast<uint32_t*>(&p0), *reinterpret_cast<uint32_t*>(&p1)};
    reinterpret_cast<uint2*>(hi)[i] = hv;
}

// ============================================================================
// fp16 2-limb GEMM core (R9-measured config): C = (Ah + Al) @ Wh^T + bias
// CTA tile 128(M) x 256(N), BK=64, 3-stage cp.async, 8 warps (warp 64x64).
// 16 mainloop iters; per kc: 12 ldsm4 + 64 mma (2 limbs share one accum).
// SMEM rows 144B padded. Stage = Ah(18432) + Al(18432) + W(36864).
// ============================================================================
#define FQ_AS 18432
#define FQ_AL_BASE (3 * FQ_AS)            // 55296
#define FQ_W_BASE  (6 * FQ_AS)            // 110592
#define FQ_BS 36864
#define FQ_TOTAL (FQ_W_BASE + 3 * FQ_BS)  // 221184

__device__ __forceinline__
void gemm_f16_core(const __half* __restrict__ Ah, const __half* __restrict__ Al,
                   const __half* __restrict__ Wh, const float* __restrict__ bias,
                   float* __restrict__ C, char* smem, float* biasS,
                   int m0, int n0) {
    const uint32_t sbase = smem_u32(smem);
    const int tid = threadIdx.x;
    const int lane = tid & 31;
    const int wid = tid >> 5;

    biasS[tid] = bias[n0 + tid];

    auto load_stage = [&](int kt, int s) {
        const int kcol = kt << 6;
        const uint32_t sah = sbase + s * FQ_AS;
        const uint32_t sal = sbase + FQ_AL_BASE + s * FQ_AS;
        const uint32_t sb = sbase + FQ_W_BASE + s * FQ_BS;
#pragma unroll
        for (int u = 0; u < 4; u++) {
            int idx = tid + (u << 8);
            int r = idx >> 3, c = idx & 7;
            cp16(sah + r * 144 + c * 16, Ah + (m0 + r) * DMODEL + kcol + c * 8);
            cp16(sal + r * 144 + c * 16, Al + (m0 + r) * DMODEL + kcol + c * 8);
        }
#pragma unroll
        for (int u = 0; u < 8; u++) {
            int idx = tid + (u << 8);
            int r = idx >> 3, c = idx & 7;
            cp16(sb + r * 144 + c * 16, Wh + (n0 + r) * DMODEL + kcol + c * 8);
        }
    };

    load_stage(0, 0);
    asm volatile("cp.async.commit_group;" ::: "memory");
    load_stage(1, 1);
    asm volatile("cp.async.commit_group;" ::: "memory");

    float d[4][8][4];
#pragma unroll
    for (int mf = 0; mf < 4; mf++)
#pragma unroll
        for (int nf = 0; nf < 8; nf++)
#pragma unroll
            for (int q = 0; q < 4; q++) d[mf][nf][q] = 0.f;

    const int warpM = (wid >> 2) << 6;
    const int warpN = (wid & 3) << 6;
    const uint32_t aLane = (warpM + (lane & 15)) * 144 + (lane >> 4) * 16;
    const uint32_t bLane = (warpN + ((lane >> 4) & 1) * 8 + (lane & 7)) * 144 +
                           ((lane >> 3) & 1) * 16;

    for (int it = 0; it < 16; ++it) {
        const int buf = it % 3;
        if (it < 15)
            asm volatile("cp.async.wait_group 1;" ::: "memory");
        else
            asm volatile("cp.async.wait_group 0;" ::: "memory");
        __syncthreads();
        if (it + 2 < 16) {
            load_stage(it + 2, (it + 2) % 3);
            asm volatile("cp.async.commit_group;" ::: "memory");
        }
        const uint32_t sah = sbase + buf * FQ_AS + aLane;
        const uint32_t sal = sbase + FQ_AL_BASE + buf * FQ_AS + aLane;
        const uint32_t sb = sbase + FQ_W_BASE + buf * FQ_BS + bLane;

#pragma unroll
        for (int kc = 0; kc < 4; kc++) {
            const uint32_t ko = kc * 32;
            uint32_t ah[4][4], al[4][4], bb[4][4];
#pragma unroll
            for (int mf = 0; mf < 4; mf++) ldsm4(ah[mf], sah + mf * 2304 + ko);
#pragma unroll
            for (int mf = 0; mf < 4; mf++) ldsm4(al[mf], sal + mf * 2304 + ko);
#pragma unroll
            for (int nf2 = 0; nf2 < 4; nf2++) ldsm4(bb[nf2], sb + nf2 * 2304 + ko);
#pragma unroll
            for (int mf = 0; mf < 4; mf++)
#pragma unroll
                for (int nf = 0; nf < 8; nf++)
                    mma_f16(d[mf][nf], ah[mf], bb[nf >> 1][(nf & 1) * 2],
                            bb[nf >> 1][(nf & 1) * 2 + 1]);
#pragma unroll
            for (int mf = 0; mf < 4; mf++)
#pragma unroll
                for (int nf = 0; nf < 8; nf++)
                    mma_f16(d[mf][nf], al[mf], bb[nf >> 1][(nf & 1) * 2],
                            bb[nf >> 1][(nf & 1) * 2 + 1]);
        }
    }

    const int rsub = lane >> 2;
    const int csub = (lane & 3) * 2;
#pragma unroll
    for (int mf = 0; mf < 4; mf++) {
#pragma unroll
        for (int nf = 0; nf < 8; nf++) {
            const int row = m0 + warpM + mf * 16 + rsub;
            const int colL = warpN + nf * 8 + csub;
            const float b0 = biasS[colL], b1 = biasS[colL + 1];
            float2 v0 = make_float2(d[mf][nf][0] + b0, d[mf][nf][1] + b1);
            float2 v1 = make_float2(d[mf][nf][2] + b0, d[mf][nf][3] + b1);
            *reinterpret_cast<float2*>(&C[(size_t)row * DMODEL + n0 + colL]) = v0;
            *reinterpret_cast<float2*>(&C[(size_t)(row + 8) * DMODEL + n0 + colL]) = v1;
        }
    }
}

// merged Q/K/V projections
__global__ __launch_bounds__(256, 1)
void gemm_qkv_f16(const __half* __restrict__ xh, const __half* __restrict__ xl,
                  const __half* __restrict__ yh, const __half* __restrict__ yl,
                  const __half* __restrict__ qwh, const __half* __restrict__ kwh,
                  const __half* __restrict__ vwh,
                  const float* __restrict__ q_b, const float* __restrict__ k_b,
                  const float* __restrict__ v_b,
                  float* __restrict__ Q, float* __restrict__ K, float* __restrict__ V) {
    extern __shared__ __align__(128) char smem[];
    __shared__ float biasS[256];
    const int z = blockIdx.z;
    const __half* Ah = (z == 2) ? yh : xh;
    const __half* Al = (z == 2) ? yl : xl;
    const __half* Wh = (z == 0) ? qwh : (z == 1) ? kwh : vwh;
    const float* bias = (z == 0) ? q_b : (z == 1) ? k_b : v_b;
    float* C = (z == 0) ? Q : (z == 1) ? K : V;
    gemm_f16_core(Ah, Al, Wh, bias, C, smem, biasS,
                  blockIdx.y << 7, blockIdx.x << 8);
}

// output projection (same core)
__global__ __launch_bounds__(256, 1)
void gemm_out_f16(const __half* __restrict__ Oh, const __half* __restrict__ Ol,
                  const __half* __restrict__ owh, const float* __restrict__ o_b,
                  float* __restrict__ out) {
    extern __shared__ __align__(128) char smem[];
    __shared__ float biasS[256];
    gemm_f16_core(Oh, Ol, owh, o_b, out, smem, biasS,
                  blockIdx.y << 7, blockIdx.x << 8);
}

// ============================================================================
// compute_m_partial: Mpart[s][g] = sum over t in [s*64,(s+1)*64) Kg[t]^T Vg[t]
// grid (32, 32), 256 threads, 4x4 per thread.
// ============================================================================
__global__ __launch_bounds__(256)
void compute_m_partial(const float* __restrict__ Kb, const float* __restrict__ Vb,
                       float* __restrict__ Mpart) {
    const int s = blockIdx.x;
    const int g = blockIdx.y;
    __shared__ float Ks[32][64];
    __shared__ float Vs[32][64];

    const int tid = threadIdx.x;
    const int tx = tid & 15;
    const int ty = tid >> 4;

    const float* Kg = Kb + g * 131072 + s * 64 * 64;
    const float* Vg = Vb + g * 131072 + s * 64 * 64;

    unsigned long long acc[4][2];
#pragma unroll
    for (int i = 0; i < 4; i++) { acc[i][0] = 0ull; acc[i][1] = 0ull; }

    for (int t0 = 0; t0 < 64; t0 += 32) {
#pragma unroll
        for (int sr = 0; sr < 2; sr++) {
            int idx = tid + (sr << 8);
            int tt = idx >> 4;
            int d4 = (idx & 15) << 2;
            *reinterpret_cast<float4*>(&Ks[tt][d4]) =
                *reinterpret_cast<const float4*>(&Kg[(t0 + tt) * 64 + d4]);
            *reinterpret_cast<float4*>(&Vs[tt][d4]) =
                *reinterpret_cast<const float4*>(&Vg[(t0 + tt) * 64 + d4]);
        }
        __syncthreads();
#pragma unroll 8
        for (int tt = 0; tt < 32; tt++) {
            float4 a = *reinterpret_cast<const float4*>(&Ks[tt][ty << 2]);
            float4 b = *reinterpret_cast<const float4*>(&Vs[tt][tx << 2]);
            unsigned long long bq0 = f32x2_pack(b.x, b.y);
            unsigned long long bq1 = f32x2_pack(b.z, b.w);
            float av[4] = {a.x, a.y, a.z, a.w};
#pragma unroll
            for (int i = 0; i < 4; i++) {
                unsigned long long ad = f32x2_dup(av[i]);
                acc[i][0] = f32x2_fma(ad, bq0, acc[i][0]);
                acc[i][1] = f32x2_fma(ad, bq1, acc[i][1]);
            }
        }
        __syncthreads();
    }

#pragma unroll
    for (int i = 0; i < 4; i++) {
        float2 v0 = f32x2_unpack(acc[i][0]);
        float2 v1 = f32x2_unpack(acc[i][1]);
        int d = (ty << 2) + i;
        int dp = tx << 2;
        float4 o = make_float4(v0.x, v0.y, v1.x, v1.y);
        *reinterpret_cast<float4*>(&Mpart[(s * 32 + g) * 4096 + d * 64 + dp]) = o;
    }
}

__global__ __launch_bounds__(256)
void reduce_m(const float* __restrict__ Mpart, float* __restrict__ M) {
    int i = blockIdx.x * 256 + threadIdx.x;
    float acc = 0.f;
#pragma unroll
    for (int s = 0; s < 32; s++) acc += Mpart[s * 131072 + i];
    M[i] = acc * 0.03125f;
}

// ============================================================================
// apply_m: O[r, j*64+d'] = sum_d Q[r, j*64+d] * M[g][d][d'],  g = r/128
// Emits fp16 hi/lo directly (feeds fp16 2-limb output GEMM).
// ============================================================================
__global__ __launch_bounds__(256)
void apply_m(const float* __restrict__ Qb, const float* __restrict__ Mb,
             __half* __restrict__ Oh, __half* __restrict__ Ol) {
    const int j = blockIdx.x;
    const int g = blockIdx.y;

    __shared__ float Qs[64][128];
    __shared__ float Ms[64][64];

    const int tid = threadIdx.x;
    const int tx = tid & 15;
    const int ty = tid >> 4;

#pragma unroll
    for (int s = 0; s < 4; s++) {
        int idx = tid + (s << 8);
        *reinterpret_cast<float4*>(&Ms[idx >> 4][(idx & 15) << 2]) =
            *reinterpret_cast<const float4*>(&Mb[g * 4096 + idx * 4]);
    }
#pragma unroll
    for (int s = 0; s < 8; s++) {
        int idx = tid + (s << 8);
        int r = idx & 127;
        int d4 = (idx >> 7) << 2;
        float4 v = *reinterpret_cast<const float4*>(
            &Qb[(g * 128 + r) * DMODEL + (j << 6) + d4]);
        Qs[d4 + 0][r] = v.x; Qs[d4 + 1][r] = v.y;
        Qs[d4 + 2][r] = v.z; Qs[d4 + 3][r] = v.w;
    }
    __syncthreads();

    unsigned long long acc[8][2];
#pragma unroll
    for (int i = 0; i < 8; i++) { acc[i][0] = 0ull; acc[i][1] = 0ull; }

#pragma unroll 4
    for (int d = 0; d < 64; d++) {
        float4 a0 = *reinterpret_cast<const float4*>(&Qs[d][ty << 3]);
        float4 a1 = *reinterpret_cast<const float4*>(&Qs[d][(ty << 3) + 4]);
        float4 b = *reinterpret_cast<const float4*>(&Ms[d][tx << 2]);
        unsigned long long bq0 = f32x2_pack(b.x, b.y);
        unsigned long long bq1 = f32x2_pack(b.z, b.w);
        float av[8] = {a0.x, a0.y, a0.z, a0.w, a1.x, a1.y, a1.z, a1.w};
#pragma unroll
        for (int i = 0; i < 8; i++) {
            unsigned long long ad = f32x2_dup(av[i]);
            acc[i][0] = f32x2_fma(ad, bq0, acc[i][0]);
            acc[i][1] = f32x2_fma(ad, bq1, acc[i][1]);
        }
    }

#pragma unroll
    for (int i = 0; i < 8; i++) {
        int r = g * 128 + (ty << 3) + i;
        float2 v0 = f32x2_unpack(acc[i][0]);
        float2 v1 = f32x2_unpack(acc[i][1]);
        float4 o = make_float4(v0.x, v0.y, v1.x, v1.y);
        uint2 hv, lv;
        split4_f16(o, hv, lv);
        int col = (j << 6) + (tx << 2);
        *reinterpret_cast<uint2*>(&Oh[r * DMODEL + col]) = hv;
        *reinterpret_cast<uint2*>(&Ol[r * DMODEL + col]) = lv;
    }
}

// ============================================================================
extern "C" void kernel_launch(void* const* d_in, const int* in_sizes, int n_in,
                              void* d_out, int out_size) {
    const float* x   = (const float*)d_in[0];
    const float* y   = (const float*)d_in[1];
    const float* q_w = (const float*)d_in[2];
    const float* q_b = (const float*)d_in[3];
    const float* k_w = (const float*)d_in[4];
    const float* k_b = (const float*)d_in[5];
    const float* v_w = (const float*)d_in[6];
    const float* v_b = (const float*)d_in[7];
    const float* o_w = (const float*)d_in[8];
    const float* o_b = (const float*)d_in[9];
    float* out = (float*)d_out;

    float *Qp, *Kp, *Vp, *Mpp, *Mp;
    cudaGetSymbolAddress((void**)&Qp, g_Q);
    cudaGetSymbolAddress((void**)&Kp, g_K);
    cudaGetSymbolAddress((void**)&Vp, g_V);
    cudaGetSymbolAddress((void**)&Mpp, g_Mpart);
    cudaGetSymbolAddress((void**)&Mp, g_M);

    __half *xh, *xl, *yh, *yl, *oh, *ol, *qwh, *kwh, *vwh, *owh;
    cudaGetSymbolAddress((void**)&xh, g_xh);  cudaGetSymbolAddress((void**)&xl, g_xl);
    cudaGetSymbolAddress((void**)&yh, g_yh);  cudaGetSymbolAddress((void**)&yl, g_yl);
    cudaGetSymbolAddress((void**)&oh, g_oh);  cudaGetSymbolAddress((void**)&ol, g_ol);
    cudaGetSymbolAddress((void**)&qwh, g_qwh);
    cudaGetSymbolAddress((void**)&kwh, g_kwh);
    cudaGetSymbolAddress((void**)&vwh, g_vwh);
    cudaGetSymbolAddress((void**)&owh, g_owh);

    cudaFuncSetAttribute(gemm_qkv_f16, cudaFuncAttributeMaxDynamicSharedMemorySize,
                         FQ_TOTAL);
    cudaFuncSetAttribute(gemm_out_f16, cudaFuncAttributeMaxDynamicSharedMemorySize,
                         FQ_TOTAL);

    const int n4_act = MROWS * DMODEL / 4;    // 1048576
    const int n4_w = DMODEL * DMODEL / 4;     // 262144

    split_act_f16<<<dim3(n4_act / 256, 2), 256>>>(x, y, xh, xl, yh, yl);
    split_w_f16<<<dim3(n4_w / 256, 4), 256>>>(q_w, k_w, v_w, o_w,
                                              qwh, kwh, vwh, owh);

    gemm_qkv_f16<<<dim3(DMODEL / 256, MROWS / 128, 3), 256, FQ_TOTAL>>>(
        xh, xl, yh, yl, qwh, kwh, vwh, q_b, k_b, v_b, Qp, Kp, Vp);

    compute_m_partial<<<dim3(32, 32), 256>>>(Kp, Vp, Mpp);
    reduce_m<<<512, 256>>>(Mpp, Mp);
    apply_m<<<dim3(16, 32), 256>>>(Qp, Mp, oh, ol);

    gemm_out_f16<<<dim3(DMODEL / 256, MROWS / 128), 256, FQ_TOTAL>>>(
        oh, ol, owh, o_b, out);
}

// round 14
// speedup vs baseline: 1.6713x; 1.4349x over previous
#include <cuda_runtime.h>
#include <cuda_fp16.h>
#include <cstdint>

// ============================================================================
// Multihead_Attention (no-softmax => fully linear) on sm_100 (generic PTX).
// R14: pure fp16 GEMMs everywhere (single limb both operands).
//      Calibrated error model (R9/R13 exact hits): each single-fp16 operand
//      adds 2.07e-4 in quadrature -> predicted 5.85e-4 total (threshold 1e-3).
//      Runtime model: dur = MMA-pass units x ~28.3us + smalls; units 8 -> 4.
// ============================================================================

#define MROWS 4096
#define DMODEL 1024

// fp32 intermediates
__device__ float g_Q[MROWS * DMODEL];
__device__ float g_K[MROWS * DMODEL];
__device__ float g_V[MROWS * DMODEL];
__device__ float g_Mpart[32 * 32 * 64 * 64];
__device__ float g_M[32 * 64 * 64];

// fp16 operands
__device__ __half g_xh[MROWS * DMODEL];
__device__ __half g_yh[MROWS * DMODEL];
__device__ __half g_oh[MROWS * DMODEL];
__device__ __half g_qwh[DMODEL * DMODEL];
__device__ __half g_kwh[DMODEL * DMODEL];
__device__ __half g_vwh[DMODEL * DMODEL];
__device__ __half g_owh[DMODEL * DMODEL];

// ---------------- generic PTX helpers ---------------------------------------
__device__ __forceinline__ uint32_t smem_u32(const void* p) {
    uint32_t a;
    asm("{ .reg .u64 t; cvta.to.shared.u64 t, %1; cvt.u32.u64 %0, t; }"
        : "=r"(a) : "l"(p));
    return a;
}
__device__ __forceinline__ void cp16(uint32_t dst, const void* src) {
    asm volatile("cp.async.cg.shared.global [%0], [%1], 16;"
                 :: "r"(dst), "l"(src) : "memory");
}
__device__ __forceinline__ void ldsm4(uint32_t (&r)[4], uint32_t addr) {
    asm volatile("ldmatrix.sync.aligned.m8n8.x4.shared.b16 {%0,%1,%2,%3}, [%4];"
                 : "=r"(r[0]), "=r"(r[1]), "=r"(r[2]), "=r"(r[3]) : "r"(addr));
}
__device__ __forceinline__ void mma_f16(float (&d)[4], const uint32_t (&a)[4],
                                        uint32_t b0, uint32_t b1) {
    asm volatile(
        "mma.sync.aligned.m16n8k16.row.col.f32.f16.f16.f32 "
        "{%0,%1,%2,%3}, {%4,%5,%6,%7}, {%8,%9}, {%0,%1,%2,%3};"
        : "+f"(d[0]), "+f"(d[1]), "+f"(d[2]), "+f"(d[3])
        : "r"(a[0]), "r"(a[1]), "r"(a[2]), "r"(a[3]), "r"(b0), "r"(b1));
}

// ---------------- f32x2 helpers ---------------------------------------------
__device__ __forceinline__ unsigned long long f32x2_dup(float x) {
    unsigned long long r; asm("mov.b64 %0, {%1, %1};" : "=l"(r) : "f"(x)); return r;
}
__device__ __forceinline__ unsigned long long f32x2_pack(float x, float y) {
    unsigned long long r; asm("mov.b64 %0, {%1, %2};" : "=l"(r) : "f"(x), "f"(y)); return r;
}
__device__ __forceinline__ unsigned long long f32x2_fma(unsigned long long a,
                                                        unsigned long long b,
                                                        unsigned long long c) {
    unsigned long long d;
    asm("fma.rn.f32x2 %0, %1, %2, %3;" : "=l"(d) : "l"(a), "l"(b), "l"(c));
    return d;
}
__device__ __forceinline__ float2 f32x2_unpack(unsigned long long v) {
    float2 r; asm("mov.b64 {%0, %1}, %2;" : "=f"(r.x), "=f"(r.y) : "l"(v)); return r;
}

// pack 4 fp32 -> fp16x4 (uint2)
__device__ __forceinline__ uint2 pack4_f16(float4 v) {
    __half2 p0 = {__float2half_rn(v.x), __float2half_rn(v.y)};
    __half2 p1 = {__float2half_rn(v.z), __float2half_rn(v.w)};
    uint2 hv;
    hv.x = *reinterpret_cast<uint32_t*>(&p0);
    hv.y = *reinterpret_cast<uint32_t*>(&p1);
    return hv;
}

// ============================================================================
// splits: fp32 -> fp16 (single limb)
// ============================================================================
__global__ __launch_bounds__(256)
void split_act_f16(const float* __restrict__ x, const float* __restrict__ y,
                   __half* __restrict__ xh, __half* __restrict__ yh) {
    const float* src = blockIdx.y ? y : x;
    __half* hi = blockIdx.y ? yh : xh;
    int i = blockIdx.x * 256 + threadIdx.x;
    float4 v = reinterpret_cast<const float4*>(src)[i];
    reinterpret_cast<uint2*>(hi)[i] = pack4_f16(v);
}

__global__ __launch_bounds__(256)
void split_w_f16(const float* __restrict__ w0, const float* __restrict__ w1,
                 const float* __restrict__ w2, const float* __restrict__ w3,
                 __half* __restrict__ h0, __half* __restrict__ h1,
                 __half* __restrict__ h2, __half* __restrict__ h3) {
    const float* src = (blockIdx.y == 0) ? w0 : (blockIdx.y == 1) ? w1
                       : (blockIdx.y == 2) ? w2 : w3;
    __half* hi = (blockIdx.y == 0) ? h0 : (blockIdx.y == 1) ? h1
                 : (blockIdx.y == 2) ? h2 : h3;
    int i = blockIdx.x * 256 + threadIdx.x;
    float4 v = reinterpret_cast<const float4*>(src)[i];
    reinterpret_cast<uint2*>(hi)[i] = pack4_f16(v);
}

// ============================================================================
// pure fp16 GEMM core: C = A @ W^T + bias
// CTA tile 128(M) x 256(N), BK=64, 3-stage cp.async, 8 warps (warp 64x64).
// 16 mainloop iters; per kc: 8 ldsm4 + 32 mma.
// SMEM rows 144B padded. Stage = A(18432) + W(36864); 3 stages = 165888 B.
// ============================================================================
#define FQ_AS 18432
#define FQ_W_BASE (3 * FQ_AS)             // 55296
#define FQ_BS 36864
#define FQ_TOTAL (FQ_W_BASE + 3 * FQ_BS)  // 165888

__device__ __forceinline__
void gemm_f16_core(const __half* __restrict__ Ah, const __half* __restrict__ Wh,
                   const float* __restrict__ bias, float* __restrict__ C,
                   char* smem, float* biasS, int m0, int n0) {
    const uint32_t sbase = smem_u32(smem);
    const int tid = threadIdx.x;
    const int lane = tid & 31;
    const int wid = tid >> 5;

    biasS[tid] = bias[n0 + tid];

    auto load_stage = [&](int kt, int s) {
        const int kcol = kt << 6;
        const uint32_t sa = sbase + s * FQ_AS;
        const uint32_t sb = sbase + FQ_W_BASE + s * FQ_BS;
#pragma unroll
        for (int u = 0; u < 4; u++) {
            int idx = tid + (u << 8);
            int r = idx >> 3, c = idx & 7;
            cp16(sa + r * 144 + c * 16, Ah + (m0 + r) * DMODEL + kcol + c * 8);
        }
#pragma unroll
        for (int u = 0; u < 8; u++) {
            int idx = tid + (u << 8);
            int r = idx >> 3, c = idx & 7;
            cp16(sb + r * 144 + c * 16, Wh + (n0 + r) * DMODEL + kcol + c * 8);
        }
    };

    load_stage(0, 0);
    asm volatile("cp.async.commit_group;" ::: "memory");
    load_stage(1, 1);
    asm volatile("cp.async.commit_group;" ::: "memory");

    float d[4][8][4];
#pragma unroll
    for (int mf = 0; mf < 4; mf++)
#pragma unroll
        for (int nf = 0; nf < 8; nf++)
#pragma unroll
            for (int q = 0; q < 4; q++) d[mf][nf][q] = 0.f;

    const int warpM = (wid >> 2) << 6;
    const int warpN = (wid & 3) << 6;
    const uint32_t aLane = (warpM + (lane & 15)) * 144 + (lane >> 4) * 16;
    const uint32_t bLane = (warpN + ((lane >> 4) & 1) * 8 + (lane & 7)) * 144 +
                           ((lane >> 3) & 1) * 16;

    for (int it = 0; it < 16; ++it) {
        const int buf = it % 3;
        if (it < 15)
            asm volatile("cp.async.wait_group 1;" ::: "memory");
        else
            asm volatile("cp.async.wait_group 0;" ::: "memory");
        __syncthreads();
        if (it + 2 < 16) {
            load_stage(it + 2, (it + 2) % 3);
            asm volatile("cp.async.commit_group;" ::: "memory");
        }
        const uint32_t sa = sbase + buf * FQ_AS + aLane;
        const uint32_t sb = sbase + FQ_W_BASE + buf * FQ_BS + bLane;

#pragma unroll
        for (int kc = 0; kc < 4; kc++) {
            const uint32_t ko = kc * 32;
            uint32_t a[4][4], bb[4][4];
#pragma unroll
            for (int mf = 0; mf < 4; mf++) ldsm4(a[mf], sa + mf * 2304 + ko);
#pragma unroll
            for (int nf2 = 0; nf2 < 4; nf2++) ldsm4(bb[nf2], sb + nf2 * 2304 + ko);
#pragma unroll
            for (int mf = 0; mf < 4; mf++)
#pragma unroll
                for (int nf = 0; nf < 8; nf++)
                    mma_f16(d[mf][nf], a[mf], bb[nf >> 1][(nf & 1) * 2],
                            bb[nf >> 1][(nf & 1) * 2 + 1]);
        }
    }

    const int rsub = lane >> 2;
    const int csub = (lane & 3) * 2;
#pragma unroll
    for (int mf = 0; mf < 4; mf++) {
#pragma unroll
        for (int nf = 0; nf < 8; nf++) {
            const int row = m0 + warpM + mf * 16 + rsub;
            const int colL = warpN + nf * 8 + csub;
            const float b0 = biasS[colL], b1 = biasS[colL + 1];
            float2 v0 = make_float2(d[mf][nf][0] + b0, d[mf][nf][1] + b1);
            float2 v1 = make_float2(d[mf][nf][2] + b0, d[mf][nf][3] + b1);
            *reinterpret_cast<float2*>(&C[(size_t)row * DMODEL + n0 + colL]) = v0;
            *reinterpret_cast<float2*>(&C[(size_t)(row + 8) * DMODEL + n0 + colL]) = v1;
        }
    }
}

// merged Q/K/V projections
__global__ __launch_bounds__(256, 1)
void gemm_qkv_f16(const __half* __restrict__ xh, const __half* __restrict__ yh,
                  const __half* __restrict__ qwh, const __half* __restrict__ kwh,
                  const __half* __restrict__ vwh,
                  const float* __restrict__ q_b, const float* __restrict__ k_b,
                  const float* __restrict__ v_b,
                  float* __restrict__ Q, float* __restrict__ K, float* __restrict__ V) {
    extern __shared__ __align__(128) char smem[];
    __shared__ float biasS[256];
    const int z = blockIdx.z;
    const __half* Ah = (z == 2) ? yh : xh;
    const __half* Wh = (z == 0) ? qwh : (z == 1) ? kwh : vwh;
    const float* bias = (z == 0) ? q_b : (z == 1) ? k_b : v_b;
    float* C = (z == 0) ? Q : (z == 1) ? K : V;
    gemm_f16_core(Ah, Wh, bias, C, smem, biasS,
                  blockIdx.y << 7, blockIdx.x << 8);
}

// output projection (same core)
__global__ __launch_bounds__(256, 1)
void gemm_out_f16(const __half* __restrict__ Oh, const __half* __restrict__ owh,
                  const float* __restrict__ o_b, float* __restrict__ out) {
    extern __shared__ __align__(128) char smem[];
    __shared__ float biasS[256];
    gemm_f16_core(Oh, owh, o_b, out, smem, biasS,
                  blockIdx.y << 7, blockIdx.x << 8);
}

// ============================================================================
// compute_m_partial: Mpart[s][g] = sum over t in [s*64,(s+1)*64) Kg[t]^T Vg[t]
// grid (32, 32), 256 threads, 4x4 per thread.
// ============================================================================
__global__ __launch_bounds__(256)
void compute_m_partial(const float* __restrict__ Kb, const float* __restrict__ Vb,
                       float* __restrict__ Mpart) {
    const int s = blockIdx.x;
    const int g = blockIdx.y;
    __shared__ float Ks[32][64];
    __shared__ float Vs[32][64];

    const int tid = threadIdx.x;
    const int tx = tid & 15;
    const int ty = tid >> 4;

    const float* Kg = Kb + g * 131072 + s * 64 * 64;
    const float* Vg = Vb + g * 131072 + s * 64 * 64;

    unsigned long long acc[4][2];
#pragma unroll
    for (int i = 0; i < 4; i++) { acc[i][0] = 0ull; acc[i][1] = 0ull; }

    for (int t0 = 0; t0 < 64; t0 += 32) {
#pragma unroll
        for (int sr = 0; sr < 2; sr++) {
            int idx = tid + (sr << 8);
            int tt = idx >> 4;
            int d4 = (idx & 15) << 2;
            *reinterpret_cast<float4*>(&Ks[tt][d4]) =
                *reinterpret_cast<const float4*>(&Kg[(t0 + tt) * 64 + d4]);
            *reinterpret_cast<float4*>(&Vs[tt][d4]) =
                *reinterpret_cast<const float4*>(&Vg[(t0 + tt) * 64 + d4]);
        }
        __syncthreads();
#pragma unroll 8
        for (int tt = 0; tt < 32; tt++) {
            float4 a = *reinterpret_cast<const float4*>(&Ks[tt][ty << 2]);
            float4 b = *reinterpret_cast<const float4*>(&Vs[tt][tx << 2]);
            unsigned long long bq0 = f32x2_pack(b.x, b.y);
            unsigned long long bq1 = f32x2_pack(b.z, b.w);
            float av[4] = {a.x, a.y, a.z, a.w};
#pragma unroll
            for (int i = 0; i < 4; i++) {
                unsigned long long ad = f32x2_dup(av[i]);
                acc[i][0] = f32x2_fma(ad, bq0, acc[i][0]);
                acc[i][1] = f32x2_fma(ad, bq1, acc[i][1]);
            }
        }
        __syncthreads();
    }

#pragma unroll
    for (int i = 0; i < 4; i++) {
        float2 v0 = f32x2_unpack(acc[i][0]);
        float2 v1 = f32x2_unpack(acc[i][1]);
        int d = (ty << 2) + i;
        int dp = tx << 2;
        float4 o = make_float4(v0.x, v0.y, v1.x, v1.y);
        *reinterpret_cast<float4*>(&Mpart[(s * 32 + g) * 4096 + d * 64 + dp]) = o;
    }
}

__global__ __launch_bounds__(256)
void reduce_m(const float* __restrict__ Mpart, float* __restrict__ M) {
    int i = blockIdx.x * 256 + threadIdx.x;
    float acc = 0.f;
#pragma unroll
    for (int s = 0; s < 32; s++) acc += Mpart[s * 131072 + i];
    M[i] = acc * 0.03125f;
}

// ============================================================================
// apply_m: O[r, j*64+d'] = sum_d Q[r, j*64+d] * M[g][d][d'],  g = r/128
// Emits fp16 directly (feeds fp16 output GEMM).
// ============================================================================
__global__ __launch_bounds__(256)
void apply_m(const float* __restrict__ Qb, const float* __restrict__ Mb,
             __half* __restrict__ Oh) {
    const int j = blockIdx.x;
    const int g = blockIdx.y;

    __shared__ float Qs[64][128];
    __shared__ float Ms[64][64];

    const int tid = threadIdx.x;
    const int tx = tid & 15;
    const int ty = tid >> 4;

#pragma unroll
    for (int s = 0; s < 4; s++) {
        int idx = tid + (s << 8);
        *reinterpret_cast<float4*>(&Ms[idx >> 4][(idx & 15) << 2]) =
            *reinterpret_cast<const float4*>(&Mb[g * 4096 + idx * 4]);
    }
#pragma unroll
    for (int s = 0; s < 8; s++) {
        int idx = tid + (s << 8);
        int r = idx & 127;
        int d4 = (idx >> 7) << 2;
        float4 v = *reinterpret_cast<const float4*>(
            &Qb[(g * 128 + r) * DMODEL + (j << 6) + d4]);
        Qs[d4 + 0][r] = v.x; Qs[d4 + 1][r] = v.y;
        Qs[d4 + 2][r] = v.z; Qs[d4 + 3][r] = v.w;
    }
    __syncthreads();

    unsigned long long acc[8][2];
#pragma unroll
    for (int i = 0; i < 8; i++) { acc[i][0] = 0ull; acc[i][1] = 0ull; }

#pragma unroll 4
    for (int d = 0; d < 64; d++) {
        float4 a0 = *reinterpret_cast<const float4*>(&Qs[d][ty << 3]);
        float4 a1 = *reinterpret_cast<const float4*>(&Qs[d][(ty << 3) + 4]);
        float4 b = *reinterpret_cast<const float4*>(&Ms[d][tx << 2]);
        unsigned long long bq0 = f32x2_pack(b.x, b.y);
        unsigned long long bq1 = f32x2_pack(b.z, b.w);
        float av[8] = {a0.x, a0.y, a0.z, a0.w, a1.x, a1.y, a1.z, a1.w};
#pragma unroll
        for (int i = 0; i < 8; i++) {
            unsigned long long ad = f32x2_dup(av[i]);
            acc[i][0] = f32x2_fma(ad, bq0, acc[i][0]);
            acc[i][1] = f32x2_fma(ad, bq1, acc[i][1]);
        }
    }

#pragma unroll
    for (int i = 0; i < 8; i++) {
        int r = g * 128 + (ty << 3) + i;
        float2 v0 = f32x2_unpack(acc[i][0]);
        float2 v1 = f32x2_unpack(acc[i][1]);
        float4 o = make_float4(v0.x, v0.y, v1.x, v1.y);
        int col = (j << 6) + (tx << 2);
        *reinterpret_cast<uint2*>(&Oh[r * DMODEL + col]) = pack4_f16(o);
    }
}

// ============================================================================
extern "C" void kernel_launch(void* const* d_in, const int* in_sizes, int n_in,
                              void* d_out, int out_size) {
    const float* x   = (const float*)d_in[0];
    const float* y   = (const float*)d_in[1];
    const float* q_w = (const float*)d_in[2];
    const float* q_b = (const float*)d_in[3];
    const float* k_w = (const float*)d_in[4];
    const float* k_b = (const float*)d_in[5];
    const float* v_w = (const float*)d_in[6];
    const float* v_b = (const float*)d_in[7];
    const float* o_w = (const float*)d_in[8];
    const float* o_b = (const float*)d_in[9];
    float* out = (float*)d_out;

    float *Qp, *Kp, *Vp, *Mpp, *Mp;
    cudaGetSymbolAddress((void**)&Qp, g_Q);
    cudaGetSymbolAddress((void**)&Kp, g_K);
    cudaGetSymbolAddress((void**)&Vp, g_V);
    cudaGetSymbolAddress((void**)&Mpp, g_Mpart);
    cudaGetSymbolAddress((void**)&Mp, g_M);

    __half *xh, *yh, *oh, *qwh, *kwh, *vwh, *owh;
    cudaGetSymbolAddress((void**)&xh, g_xh);
    cudaGetSymbolAddress((void**)&yh, g_yh);
    cudaGetSymbolAddress((void**)&oh, g_oh);
    cudaGetSymbolAddress((void**)&qwh, g_qwh);
    cudaGetSymbolAddress((void**)&kwh, g_kwh);
    cudaGetSymbolAddress((void**)&vwh, g_vwh);
    cudaGetSymbolAddress((void**)&owh, g_owh);

    cudaFuncSetAttribute(gemm_qkv_f16, cudaFuncAttributeMaxDynamicSharedMemorySize,
                         FQ_TOTAL);
    cudaFuncSetAttribute(gemm_out_f16, cudaFuncAttributeMaxDynamicSharedMemorySize,
                         FQ_TOTAL);

    const int n4_act = MROWS * DMODEL / 4;    // 1048576
    const int n4_w = DMODEL * DMODEL / 4;     // 262144

    split_act_f16<<<dim3(n4_act / 256, 2), 256>>>(x, y, xh, yh);
    split_w_f16<<<dim3(n4_w / 256, 4), 256>>>(q_w, k_w, v_w, o_w,
                                              qwh, kwh, vwh, owh);

    gemm_qkv_f16<<<dim3(DMODEL / 256, MROWS / 128, 3), 256, FQ_TOTAL>>>(
        xh, yh, qwh, kwh, vwh, q_b, k_b, v_b, Qp, Kp, Vp);

    compute_m_partial<<<dim3(32, 32), 256>>>(Kp, Vp, Mpp);
    reduce_m<<<512, 256>>>(Mpp, Mp);
    apply_m<<<dim3(16, 32), 256>>>(Qp, Mp, oh);

    gemm_out_f16<<<dim3(DMODEL / 256, MROWS / 128), 256, FQ_TOTAL>>>(
        oh, owh, o_b, out);
}

// round 16
// speedup vs baseline: 1.8703x; 1.1191x over previous
#include <cuda_runtime.h>
#include <cuda_fp16.h>
#include <cstdint>

// ============================================================================
// Multihead_Attention (no-softmax => fully linear) on sm_100 (generic PTX).
// R16: R15 pipeline with compute_mT rebuilt on PROVEN ldmatrix addressing:
//   transpose K/V during smem fill (scalar scatter, 272B padded rows), then
//   plain non-trans ldsm4 with the 4x-validated GEMM lane formulas.
//   (R15's hand-derived ldmatrix.trans addressing produced garbage.)
// Error model: sqrt(13) * 2.07e-4 ~ 7.5e-4 (threshold 1e-3).
// Runtime model: 4 GEMM units (~118us) + ~25us smalls => ~155us.
// ============================================================================

#define MROWS 4096
#define DMODEL 1024

__device__ float g_Mpart[16 * 32 * 64 * 64];     // M^T partials (fp32)
__device__ __half g_MTh[32 * 64 * 64];           // M^T fp16

__device__ __half g_xh[MROWS * DMODEL];
__device__ __half g_yh[MROWS * DMODEL];
__device__ __half g_Qh[MROWS * DMODEL];
__device__ __half g_Kh[MROWS * DMODEL];
__device__ __half g_Vh[MROWS * DMODEL];
__device__ __half g_Oh[MROWS * DMODEL];
__device__ __half g_qwh[DMODEL * DMODEL];
__device__ __half g_kwh[DMODEL * DMODEL];
__device__ __half g_vwh[DMODEL * DMODEL];
__device__ __half g_owh[DMODEL * DMODEL];

// ---------------- generic PTX helpers ---------------------------------------
__device__ __forceinline__ uint32_t smem_u32(const void* p) {
    uint32_t a;
    asm("{ .reg .u64 t; cvta.to.shared.u64 t, %1; cvt.u32.u64 %0, t; }"
        : "=r"(a) : "l"(p));
    return a;
}
__device__ __forceinline__ void cp16(uint32_t dst, const void* src) {
    asm volatile("cp.async.cg.shared.global [%0], [%1], 16;"
                 :: "r"(dst), "l"(src) : "memory");
}
__device__ __forceinline__ void ldsm4(uint32_t (&r)[4], uint32_t addr) {
    asm volatile("ldmatrix.sync.aligned.m8n8.x4.shared.b16 {%0,%1,%2,%3}, [%4];"
                 : "=r"(r[0]), "=r"(r[1]), "=r"(r[2]), "=r"(r[3]) : "r"(addr));
}
__device__ __forceinline__ void mma_f16(float (&d)[4], const uint32_t (&a)[4],
                                        uint32_t b0, uint32_t b1) {
    asm volatile(
        "mma.sync.aligned.m16n8k16.row.col.f32.f16.f16.f32 "
        "{%0,%1,%2,%3}, {%4,%5,%6,%7}, {%8,%9}, {%0,%1,%2,%3};"
        : "+f"(d[0]), "+f"(d[1]), "+f"(d[2]), "+f"(d[3])
        : "r"(a[0]), "r"(a[1]), "r"(a[2]), "r"(a[3]), "r"(b0), "r"(b1));
}

// pack 4 fp32 -> fp16x4 (uint2)
__device__ __forceinline__ uint2 pack4_f16(float4 v) {
    __half2 p0 = __floats2half2_rn(v.x, v.y);
    __half2 p1 = __floats2half2_rn(v.z, v.w);
    uint2 hv;
    hv.x = *reinterpret_cast<uint32_t*>(&p0);
    hv.y = *reinterpret_cast<uint32_t*>(&p1);
    return hv;
}

// ============================================================================
// splits: fp32 -> fp16
// ============================================================================
__global__ __launch_bounds__(256)
void split_act_f16(const float* __restrict__ x, const float* __restrict__ y,
                   __half* __restrict__ xh, __half* __restrict__ yh) {
    const float* src = blockIdx.y ? y : x;
    __half* hi = blockIdx.y ? yh : xh;
    int i = blockIdx.x * 256 + threadIdx.x;
    float4 v = reinterpret_cast<const float4*>(src)[i];
    reinterpret_cast<uint2*>(hi)[i] = pack4_f16(v);
}

__global__ __launch_bounds__(256)
void split_w_f16(const float* __restrict__ w0, const float* __restrict__ w1,
                 const float* __restrict__ w2, const float* __restrict__ w3,
                 __half* __restrict__ h0, __half* __restrict__ h1,
                 __half* __restrict__ h2, __half* __restrict__ h3) {
    const float* src = (blockIdx.y == 0) ? w0 : (blockIdx.y == 1) ? w1
                       : (blockIdx.y == 2) ? w2 : w3;
    __half* hi = (blockIdx.y == 0) ? h0 : (blockIdx.y == 1) ? h1
                 : (blockIdx.y == 2) ? h2 : h3;
    int i = blockIdx.x * 256 + threadIdx.x;
    float4 v = reinterpret_cast<const float4*>(src)[i];
    reinterpret_cast<uint2*>(hi)[i] = pack4_f16(v);
}

// ============================================================================
// pure fp16 GEMM core (R14-proven): C = A @ W^T + bias, templated output type.
// CTA tile 128x256, BK=64, 3-stage cp.async, 8 warps.
// ============================================================================
#define FQ_AS 18432
#define FQ_W_BASE (3 * FQ_AS)
#define FQ_BS 36864
#define FQ_TOTAL (FQ_W_BASE + 3 * FQ_BS)  // 165888

template <bool HALF_OUT>
__device__ __forceinline__
void gemm_f16_core(const __half* __restrict__ Ah, const __half* __restrict__ Wh,
                   const float* __restrict__ bias, void* __restrict__ Cv,
                   char* smem, float* biasS, int m0, int n0) {
    const uint32_t sbase = smem_u32(smem);
    const int tid = threadIdx.x;
    const int lane = tid & 31;
    const int wid = tid >> 5;

    biasS[tid] = bias[n0 + tid];

    auto load_stage = [&](int kt, int s) {
        const int kcol = kt << 6;
        const uint32_t sa = sbase + s * FQ_AS;
        const uint32_t sb = sbase + FQ_W_BASE + s * FQ_BS;
#pragma unroll
        for (int u = 0; u < 4; u++) {
            int idx = tid + (u << 8);
            int r = idx >> 3, c = idx & 7;
            cp16(sa + r * 144 + c * 16, Ah + (m0 + r) * DMODEL + kcol + c * 8);
        }
#pragma unroll
        for (int u = 0; u < 8; u++) {
            int idx = tid + (u << 8);
            int r = idx >> 3, c = idx & 7;
            cp16(sb + r * 144 + c * 16, Wh + (n0 + r) * DMODEL + kcol + c * 8);
        }
    };

    load_stage(0, 0);
    asm volatile("cp.async.commit_group;" ::: "memory");
    load_stage(1, 1);
    asm volatile("cp.async.commit_group;" ::: "memory");

    float d[4][8][4];
#pragma unroll
    for (int mf = 0; mf < 4; mf++)
#pragma unroll
        for (int nf = 0; nf < 8; nf++)
#pragma unroll
            for (int q = 0; q < 4; q++) d[mf][nf][q] = 0.f;

    const int warpM = (wid >> 2) << 6;
    const int warpN = (wid & 3) << 6;
    const uint32_t aLane = (warpM + (lane & 15)) * 144 + (lane >> 4) * 16;
    const uint32_t bLane = (warpN + ((lane >> 4) & 1) * 8 + (lane & 7)) * 144 +
                           ((lane >> 3) & 1) * 16;

    for (int it = 0; it < 16; ++it) {
        const int buf = it % 3;
        if (it < 15)
            asm volatile("cp.async.wait_group 1;" ::: "memory");
        else
            asm volatile("cp.async.wait_group 0;" ::: "memory");
        __syncthreads();
        if (it + 2 < 16) {
            load_stage(it + 2, (it + 2) % 3);
            asm volatile("cp.async.commit_group;" ::: "memory");
        }
        const uint32_t sa = sbase + buf * FQ_AS + aLane;
        const uint32_t sb = sbase + FQ_W_BASE + buf * FQ_BS + bLane;

#pragma unroll
        for (int kc = 0; kc < 4; kc++) {
            const uint32_t ko = kc * 32;
            uint32_t a[4][4], bb[4][4];
#pragma unroll
            for (int mf = 0; mf < 4; mf++) ldsm4(a[mf], sa + mf * 2304 + ko);
#pragma unroll
            for (int nf2 = 0; nf2 < 4; nf2++) ldsm4(bb[nf2], sb + nf2 * 2304 + ko);
#pragma unroll
            for (int mf = 0; mf < 4; mf++)
#pragma unroll
                for (int nf = 0; nf < 8; nf++)
                    mma_f16(d[mf][nf], a[mf], bb[nf >> 1][(nf & 1) * 2],
                            bb[nf >> 1][(nf & 1) * 2 + 1]);
        }
    }

    const int rsub = lane >> 2;
    const int csub = (lane & 3) * 2;
#pragma unroll
    for (int mf = 0; mf < 4; mf++) {
#pragma unroll
        for (int nf = 0; nf < 8; nf++) {
            const int row = m0 + warpM + mf * 16 + rsub;
            const int colL = warpN + nf * 8 + csub;
            const float b0 = biasS[colL], b1 = biasS[colL + 1];
            if (HALF_OUT) {
                __half* C = (__half*)Cv;
                __half2 v0 = __floats2half2_rn(d[mf][nf][0] + b0, d[mf][nf][1] + b1);
                __half2 v1 = __floats2half2_rn(d[mf][nf][2] + b0, d[mf][nf][3] + b1);
                *reinterpret_cast<__half2*>(&C[(size_t)row * DMODEL + n0 + colL]) = v0;
                *reinterpret_cast<__half2*>(&C[(size_t)(row + 8) * DMODEL + n0 + colL]) = v1;
            } else {
                float* C = (float*)Cv;
                float2 v0 = make_float2(d[mf][nf][0] + b0, d[mf][nf][1] + b1);
                float2 v1 = make_float2(d[mf][nf][2] + b0, d[mf][nf][3] + b1);
                *reinterpret_cast<float2*>(&C[(size_t)row * DMODEL + n0 + colL]) = v0;
                *reinterpret_cast<float2*>(&C[(size_t)(row + 8) * DMODEL + n0 + colL]) = v1;
            }
        }
    }
}

// merged Q/K/V projections (fp16 outputs)
__global__ __launch_bounds__(256, 1)
void gemm_qkv_f16(const __half* __restrict__ xh, const __half* __restrict__ yh,
                  const __half* __restrict__ qwh, const __half* __restrict__ kwh,
                  const __half* __restrict__ vwh,
                  const float* __restrict__ q_b, const float* __restrict__ k_b,
                  const float* __restrict__ v_b,
                  __half* __restrict__ Q, __half* __restrict__ K,
                  __half* __restrict__ V) {
    extern __shared__ __align__(128) char smem[];
    __shared__ float biasS[256];
    const int z = blockIdx.z;
    const __half* Ah = (z == 2) ? yh : xh;
    const __half* Wh = (z == 0) ? qwh : (z == 1) ? kwh : vwh;
    const float* bias = (z == 0) ? q_b : (z == 1) ? k_b : v_b;
    __half* C = (z == 0) ? Q : (z == 1) ? K : V;
    gemm_f16_core<true>(Ah, Wh, bias, C, smem, biasS,
                        blockIdx.y << 7, blockIdx.x << 8);
}

// output projection (fp32 output)
__global__ __launch_bounds__(256, 1)
void gemm_out_f16(const __half* __restrict__ Oh, const __half* __restrict__ owh,
                  const float* __restrict__ o_b, float* __restrict__ out) {
    extern __shared__ __align__(128) char smem[];
    __shared__ float biasS[256];
    gemm_f16_core<false>(Oh, owh, o_b, out, smem, biasS,
                         blockIdx.y << 7, blockIdx.x << 8);
}

// ============================================================================
// compute_mT: MT_g[d',d] partial = sum over t-slice of V[t,d'] K[t,d]  (HMMA)
// K/V transposed during smem fill -> plain non-trans ldmatrix with the
// PROVEN lane addressing (272B padded rows: 68-word stride, conflict-free).
// grid (16, 32): s = t-slice of 128, g = group. 8 warps: wm (4 x m16),
// wn (2 x n32). A = V^T rows d', cols t. B = K^T rows d, cols t.
// ============================================================================
__global__ __launch_bounds__(256)
void compute_mT(const __half* __restrict__ Kh, const __half* __restrict__ Vh,
                float* __restrict__ Mpart) {
    __shared__ __align__(16) __half KsT[64 * 136];
    __shared__ __align__(16) __half VsT[64 * 136];
    const int s = blockIdx.x;
    const int g = blockIdx.y;
    const int tid = threadIdx.x;
    const int lane = tid & 31;
    const int wid = tid >> 5;

    const int gsrc = g * 131072 + s * 8192;   // halves offset

    // transposed fill: read [t][d] 8 halves, scatter to [d][t]
#pragma unroll
    for (int u = 0; u < 4; u++) {
        int idx = tid + (u << 8);        // 0..1023
        int t = idx & 127;
        int d8 = (idx >> 7) << 3;        // 0..56 step 8
        float4 kv = *reinterpret_cast<const float4*>(&Kh[gsrc + t * 64 + d8]);
        float4 vv = *reinterpret_cast<const float4*>(&Vh[gsrc + t * 64 + d8]);
        const __half* kp = reinterpret_cast<const __half*>(&kv);
        const __half* vp = reinterpret_cast<const __half*>(&vv);
#pragma unroll
        for (int e = 0; e < 8; e++) {
            KsT[(d8 + e) * 136 + t] = kp[e];
            VsT[(d8 + e) * 136 + t] = vp[e];
        }
    }
    __syncthreads();

    const uint32_t sK = smem_u32(KsT);
    const uint32_t sV = smem_u32(VsT);
    const int wm = wid >> 1;   // d' 16-slice (0..3)
    const int wn = wid & 1;    // d 32-slice (0..1)

    // PROVEN non-trans addressing (row stride 272B)
    const uint32_t aLane = sV + (wm * 16 + (lane & 15)) * 272 + (lane >> 4) * 16;
    const uint32_t bLane = sK + (wn * 32 + ((lane >> 4) & 1) * 8 + (lane & 7)) * 272 +
                           ((lane >> 3) & 1) * 16;

    float d[4][4];
#pragma unroll
    for (int nf = 0; nf < 4; nf++)
#pragma unroll
        for (int q = 0; q < 4; q++) d[nf][q] = 0.f;

#pragma unroll
    for (int kc = 0; kc < 8; kc++) {     // k = t = 128 = 8 x 16
        const uint32_t ko = kc * 32;
        uint32_t a[4], bb[2][4];
        ldsm4(a, aLane + ko);
        ldsm4(bb[0], bLane + ko);
        ldsm4(bb[1], bLane + ko + 16 * 272);
#pragma unroll
        for (int nf = 0; nf < 4; nf++)
            mma_f16(d[nf], a, bb[nf >> 1][(nf & 1) * 2],
                    bb[nf >> 1][(nf & 1) * 2 + 1]);
    }

    const int rsub = lane >> 2;
    const int csub = (lane & 3) * 2;
    float* dst = Mpart + (size_t)(s * 32 + g) * 4096;
#pragma unroll
    for (int nf = 0; nf < 4; nf++) {
        int dp = wm * 16 + rsub;
        int dc = wn * 32 + nf * 8 + csub;
        *reinterpret_cast<float2*>(&dst[dp * 64 + dc]) =
            make_float2(d[nf][0], d[nf][1]);
        *reinterpret_cast<float2*>(&dst[(dp + 8) * 64 + dc]) =
            make_float2(d[nf][2], d[nf][3]);
    }
}

// reduce 16 partials, scale 1/32, emit fp16 M^T
__global__ __launch_bounds__(256)
void reduce_mT(const float* __restrict__ Mpart, __half* __restrict__ MTh) {
    int i = blockIdx.x * 256 + threadIdx.x;  // 131072
    float acc = 0.f;
#pragma unroll
    for (int s = 0; s < 16; s++) acc += Mpart[s * 131072 + i];
    MTh[i] = __float2half_rn(acc * 0.03125f);
}

// ============================================================================
// apply_mma: O[r, j*64+d'] = sum_d Q[r, j*64+d] * M[d][d']   (HMMA)
// grid (16, 32). A = Qh tile (k-major), B = MTh (k-major). Proven addressing.
// ============================================================================
__global__ __launch_bounds__(256)
void apply_mma(const __half* __restrict__ Qh, const __half* __restrict__ MTh,
               __half* __restrict__ Oh) {
    __shared__ __align__(16) __half Qs[128 * 72];
    __shared__ __align__(16) __half Ms[64 * 72];
    const int j = blockIdx.x;
    const int g = blockIdx.y;
    const int tid = threadIdx.x;
    const int lane = tid & 31;
    const int wid = tid >> 5;

    const uint32_t sQ = smem_u32(Qs);
    const uint32_t sM = smem_u32(Ms);

#pragma unroll
    for (int u = 0; u < 4; u++) {
        int idx = tid + (u << 8);
        int r = idx >> 3, c = idx & 7;
        *reinterpret_cast<float4*>(&Qs[r * 72 + c * 8]) =
            *reinterpret_cast<const float4*>(
                &Qh[(size_t)(g * 128 + r) * DMODEL + (j << 6) + c * 8]);
    }
#pragma unroll
    for (int u = 0; u < 2; u++) {
        int idx = tid + (u << 8);
        int r = idx >> 3, c = idx & 7;
        *reinterpret_cast<float4*>(&Ms[r * 72 + c * 8]) =
            *reinterpret_cast<const float4*>(&MTh[g * 4096 + r * 64 + c * 8]);
    }
    __syncthreads();

    const int wm = wid;
    const uint32_t aLane = sQ + (wm * 16 + (lane & 15)) * 144 + (lane >> 4) * 16;
    const uint32_t bLane = sM + (((lane >> 4) & 1) * 8 + (lane & 7)) * 144 +
                           ((lane >> 3) & 1) * 16;

    float d[8][4];
#pragma unroll
    for (int nf = 0; nf < 8; nf++)
#pragma unroll
        for (int q = 0; q < 4; q++) d[nf][q] = 0.f;

#pragma unroll
    for (int kc = 0; kc < 4; kc++) {
        const uint32_t ko = kc * 32;
        uint32_t a[4], bb[4][4];
        ldsm4(a, aLane + ko);
#pragma unroll
        for (int nf2 = 0; nf2 < 4; nf2++) ldsm4(bb[nf2], bLane + nf2 * 2304 + ko);
#pragma unroll
        for (int nf = 0; nf < 8; nf++)
            mma_f16(d[nf], a, bb[nf >> 1][(nf & 1) * 2],
                    bb[nf >> 1][(nf & 1) * 2 + 1]);
    }

    const int rsub = lane >> 2;
    const int csub = (lane & 3) * 2;
#pragma unroll
    for (int nf = 0; nf < 8; nf++) {
        int row = g * 128 + wm * 16 + rsub;
        int col = (j << 6) + nf * 8 + csub;
        __half2 v0 = __floats2half2_rn(d[nf][0], d[nf][1]);
        __half2 v1 = __floats2half2_rn(d[nf][2], d[nf][3]);
        *reinterpret_cast<__half2*>(&Oh[(size_t)row * DMODEL + col]) = v0;
        *reinterpret_cast<__half2*>(&Oh[(size_t)(row + 8) * DMODEL + col]) = v1;
    }
}

// ============================================================================
extern "C" void kernel_launch(void* const* d_in, const int* in_sizes, int n_in,
                              void* d_out, int out_size) {
    const float* x   = (const float*)d_in[0];
    const float* y   = (const float*)d_in[1];
    const float* q_w = (const float*)d_in[2];
    const float* q_b = (const float*)d_in[3];
    const float* k_w = (const float*)d_in[4];
    const float* k_b = (const float*)d_in[5];
    const float* v_w = (const float*)d_in[6];
    const float* v_b = (const float*)d_in[7];
    const float* o_w = (const float*)d_in[8];
    const float* o_b = (const float*)d_in[9];
    float* out = (float*)d_out;

    float* Mpp;
    __half *MTh, *xh, *yh, *Qh, *Kh, *Vh, *Oh, *qwh, *kwh, *vwh, *owh;
    cudaGetSymbolAddress((void**)&Mpp, g_Mpart);
    cudaGetSymbolAddress((void**)&MTh, g_MTh);
    cudaGetSymbolAddress((void**)&xh, g_xh);
    cudaGetSymbolAddress((void**)&yh, g_yh);
    cudaGetSymbolAddress((void**)&Qh, g_Qh);
    cudaGetSymbolAddress((void**)&Kh, g_Kh);
    cudaGetSymbolAddress((void**)&Vh, g_Vh);
    cudaGetSymbolAddress((void**)&Oh, g_Oh);
    cudaGetSymbolAddress((void**)&qwh, g_qwh);
    cudaGetSymbolAddress((void**)&kwh, g_kwh);
    cudaGetSymbolAddress((void**)&vwh, g_vwh);
    cudaGetSymbolAddress((void**)&owh, g_owh);

    cudaFuncSetAttribute(gemm_qkv_f16, cudaFuncAttributeMaxDynamicSharedMemorySize,
                         FQ_TOTAL);
    cudaFuncSetAttribute(gemm_out_f16, cudaFuncAttributeMaxDynamicSharedMemorySize,
                         FQ_TOTAL);

    const int n4_act = MROWS * DMODEL / 4;    // 1048576
    const int n4_w = DMODEL * DMODEL / 4;     // 262144

    split_act_f16<<<dim3(n4_act / 256, 2), 256>>>(x, y, xh, yh);
    split_w_f16<<<dim3(n4_w / 256, 4), 256>>>(q_w, k_w, v_w, o_w,
                                              qwh, kwh, vwh, owh);

    gemm_qkv_f16<<<dim3(DMODEL / 256, MROWS / 128, 3), 256, FQ_TOTAL>>>(
        xh, yh, qwh, kwh, vwh, q_b, k_b, v_b, Qh, Kh, Vh);

    compute_mT<<<dim3(16, 32), 256>>>(Kh, Vh, Mpp);
    reduce_mT<<<512, 256>>>(Mpp, MTh);
    apply_mma<<<dim3(16, 32), 256>>>(Qh, MTh, Oh);

    gemm_out_f16<<<dim3(DMODEL / 256, MROWS / 128), 256, FQ_TOTAL>>>(
        Oh, owh, o_b, out);
}